// round 1
// baseline (speedup 1.0000x reference)
#include <cuda_runtime.h>
#include <math.h>

// Problem constants
#define BATCH   8
#define SEQ     2048
#define DIM     512          // dim_val == dim_attn == 512
#define MTOT    (BATCH * SEQ)    // 16384

// GEMM tiling
#define BM 128
#define BN 128
#define BKK 8
#define TM 8
#define TN 8

// Scratch (allocation-free: device globals)
__device__ float g_Q[(size_t)BATCH * SEQ * DIM];
__device__ float g_K[(size_t)BATCH * SEQ * DIM];
__device__ float g_V[(size_t)BATCH * SEQ * DIM];
__device__ float g_S[(size_t)BATCH * SEQ * SEQ];   // scores / attn (134 MB)

// ---------------------------------------------------------------------------
// C[M,N] = alpha * A[M,K] * B^T   where B is stored [N,K] (row-major, K-contig)
// Exact tiles only: M%128==0, N%128==0, K%8==0, K%4==0 for float4 loads.
// blockIdx.z selects batch via element strides.
// ---------------------------------------------------------------------------
__global__ __launch_bounds__(256) void sgemm_nt(
    const float* __restrict__ A, const float* __restrict__ B, float* __restrict__ C,
    int M, int N, int K, size_t sA, size_t sB, size_t sC, float alpha)
{
    A += (size_t)blockIdx.z * sA;
    B += (size_t)blockIdx.z * sB;
    C += (size_t)blockIdx.z * sC;

    __shared__ float As[BKK][BM];
    __shared__ float Bs[BKK][BN];

    const int tid  = threadIdx.x;
    const int row0 = blockIdx.y * BM;
    const int col0 = blockIdx.x * BN;

    // loader mapping: 256 threads, each loads a float4 along K
    const int l_r = tid >> 1;          // 0..127 (tile row / tile col)
    const int l_c = (tid & 1) * 4;     // 0 or 4 within BK=8

    const int ty = tid >> 4;           // 0..15
    const int tx = tid & 15;           // 0..15

    float acc[TM][TN];
    #pragma unroll
    for (int i = 0; i < TM; i++)
        #pragma unroll
        for (int j = 0; j < TN; j++) acc[i][j] = 0.f;

    for (int k0 = 0; k0 < K; k0 += BKK) {
        float4 av = *(const float4*)&A[(size_t)(row0 + l_r) * K + k0 + l_c];
        As[l_c + 0][l_r] = av.x;
        As[l_c + 1][l_r] = av.y;
        As[l_c + 2][l_r] = av.z;
        As[l_c + 3][l_r] = av.w;

        float4 bv = *(const float4*)&B[(size_t)(col0 + l_r) * K + k0 + l_c];
        Bs[l_c + 0][l_r] = bv.x;
        Bs[l_c + 1][l_r] = bv.y;
        Bs[l_c + 2][l_r] = bv.z;
        Bs[l_c + 3][l_r] = bv.w;

        __syncthreads();

        #pragma unroll
        for (int k = 0; k < BKK; k++) {
            float a[TM], b[TN];
            #pragma unroll
            for (int i = 0; i < TM; i++) a[i] = As[k][ty * TM + i];
            #pragma unroll
            for (int j = 0; j < TN; j++) b[j] = Bs[k][tx * TN + j];
            #pragma unroll
            for (int i = 0; i < TM; i++)
                #pragma unroll
                for (int j = 0; j < TN; j++) acc[i][j] = fmaf(a[i], b[j], acc[i][j]);
        }
        __syncthreads();
    }

    #pragma unroll
    for (int i = 0; i < TM; i++) {
        const size_t crow = (size_t)(row0 + ty * TM + i) * N + col0 + tx * TN;
        float4 v0 = make_float4(alpha * acc[i][0], alpha * acc[i][1],
                                alpha * acc[i][2], alpha * acc[i][3]);
        float4 v1 = make_float4(alpha * acc[i][4], alpha * acc[i][5],
                                alpha * acc[i][6], alpha * acc[i][7]);
        *(float4*)&C[crow + 0] = v0;
        *(float4*)&C[crow + 4] = v1;
    }
}

// ---------------------------------------------------------------------------
// C[M,N] = A[M,K] * B[K,N]   (B row-major, N-contiguous)
// ---------------------------------------------------------------------------
__global__ __launch_bounds__(256) void sgemm_nn(
    const float* __restrict__ A, const float* __restrict__ B, float* __restrict__ C,
    int M, int N, int K, size_t sA, size_t sB, size_t sC)
{
    A += (size_t)blockIdx.z * sA;
    B += (size_t)blockIdx.z * sB;
    C += (size_t)blockIdx.z * sC;

    __shared__ float As[BKK][BM];
    __shared__ float Bs[BKK][BN];

    const int tid  = threadIdx.x;
    const int row0 = blockIdx.y * BM;
    const int col0 = blockIdx.x * BN;

    const int la_r = tid >> 1;          // A tile row 0..127
    const int la_c = (tid & 1) * 4;     // k within BK

    const int lb_k = tid >> 5;          // 0..7
    const int lb_n = (tid & 31) * 4;    // 0..124

    const int ty = tid >> 4;
    const int tx = tid & 15;

    float acc[TM][TN];
    #pragma unroll
    for (int i = 0; i < TM; i++)
        #pragma unroll
        for (int j = 0; j < TN; j++) acc[i][j] = 0.f;

    for (int k0 = 0; k0 < K; k0 += BKK) {
        float4 av = *(const float4*)&A[(size_t)(row0 + la_r) * K + k0 + la_c];
        As[la_c + 0][la_r] = av.x;
        As[la_c + 1][la_r] = av.y;
        As[la_c + 2][la_r] = av.z;
        As[la_c + 3][la_r] = av.w;

        float4 bv = *(const float4*)&B[(size_t)(k0 + lb_k) * N + col0 + lb_n];
        *(float4*)&Bs[lb_k][lb_n] = bv;

        __syncthreads();

        #pragma unroll
        for (int k = 0; k < BKK; k++) {
            float a[TM], b[TN];
            #pragma unroll
            for (int i = 0; i < TM; i++) a[i] = As[k][ty * TM + i];
            #pragma unroll
            for (int j = 0; j < TN; j++) b[j] = Bs[k][tx * TN + j];
            #pragma unroll
            for (int i = 0; i < TM; i++)
                #pragma unroll
                for (int j = 0; j < TN; j++) acc[i][j] = fmaf(a[i], b[j], acc[i][j]);
        }
        __syncthreads();
    }

    #pragma unroll
    for (int i = 0; i < TM; i++) {
        const size_t crow = (size_t)(row0 + ty * TM + i) * N + col0 + tx * TN;
        *(float4*)&C[crow + 0] = make_float4(acc[i][0], acc[i][1], acc[i][2], acc[i][3]);
        *(float4*)&C[crow + 4] = make_float4(acc[i][4], acc[i][5], acc[i][6], acc[i][7]);
    }
}

// ---------------------------------------------------------------------------
// In-place row softmax. One block per row of length n.
// ---------------------------------------------------------------------------
__global__ __launch_bounds__(256) void softmax_rows(float* __restrict__ S, int n)
{
    float* row = S + (size_t)blockIdx.x * n;
    __shared__ float red[256];
    const int tid = threadIdx.x;

    float m = -INFINITY;
    for (int i = tid; i < n; i += 256) m = fmaxf(m, row[i]);
    red[tid] = m;
    __syncthreads();
    #pragma unroll
    for (int s = 128; s > 0; s >>= 1) {
        if (tid < s) red[tid] = fmaxf(red[tid], red[tid + s]);
        __syncthreads();
    }
    m = red[0];
    __syncthreads();

    float sum = 0.f;
    for (int i = tid; i < n; i += 256) {
        float e = __expf(row[i] - m);
        row[i] = e;
        sum += e;
    }
    red[tid] = sum;
    __syncthreads();
    #pragma unroll
    for (int s = 128; s > 0; s >>= 1) {
        if (tid < s) red[tid] += red[tid + s];
        __syncthreads();
    }
    const float inv = 1.f / red[0];
    __syncthreads();

    for (int i = tid; i < n; i += 256) row[i] *= inv;
}

// ---------------------------------------------------------------------------
extern "C" void kernel_launch(void* const* d_in, const int* in_sizes, int n_in,
                              void* d_out, int out_size)
{
    const float* x  = (const float*)d_in[0];
    const float* Wq = (const float*)d_in[1];
    const float* Wk = (const float*)d_in[2];
    const float* Wv = (const float*)d_in[3];
    float* out = (float*)d_out;

    float *Q, *K, *V, *S;
    cudaGetSymbolAddress((void**)&Q, g_Q);
    cudaGetSymbolAddress((void**)&K, g_K);
    cudaGetSymbolAddress((void**)&V, g_V);
    cudaGetSymbolAddress((void**)&S, g_S);

    const float scale = 0.044194173824159216f;   // 1/sqrt(512)

    // --- QKV projections: [16384,512] = x[16384,512] @ W^T[512,512] ---
    {
        dim3 grid(DIM / BN, MTOT / BM, 1);
        sgemm_nt<<<grid, 256>>>(x, Wq, Q, MTOT, DIM, DIM, 0, 0, 0, 1.0f);
        sgemm_nt<<<grid, 256>>>(x, Wk, K, MTOT, DIM, DIM, 0, 0, 0, 1.0f);
        sgemm_nt<<<grid, 256>>>(x, Wv, V, MTOT, DIM, DIM, 0, 0, 0, 1.0f);
    }

    // --- scores = Q @ K^T / sqrt(d): per-batch [2048,2048], K=512 ---
    {
        dim3 grid(SEQ / BN, SEQ / BM, BATCH);
        sgemm_nt<<<grid, 256>>>(Q, K, S, SEQ, SEQ, DIM,
                                (size_t)SEQ * DIM, (size_t)SEQ * DIM,
                                (size_t)SEQ * SEQ, scale);
    }

    // --- softmax over last dim ---
    softmax_rows<<<BATCH * SEQ, 256>>>(S, SEQ);

    // --- out = attn @ V: per-batch [2048,512], K=2048 ---
    {
        dim3 grid(DIM / BN, SEQ / BM, BATCH);
        sgemm_nn<<<grid, 256>>>(S, V, out, SEQ, DIM, SEQ,
                                (size_t)SEQ * SEQ, (size_t)SEQ * DIM,
                                (size_t)SEQ * DIM);
    }
}

// round 3
// speedup vs baseline: 2.2722x; 2.2722x over previous
#include <cuda_runtime.h>
#include <cuda_bf16.h>
#include <math.h>
#include <stdint.h>

#define BATCH 8
#define SEQ   2048
#define DIM   512
#define MTOT  (BATCH*SEQ)        // 16384

// ===========================================================================
// Scratch memory (single __device__ array; no allocation anywhere)
// ===========================================================================
#define SZ_X ((size_t)MTOT * DIM)                     // 8,388,608 elems
static const size_t O_XHI  = 0;                               // bf16 SZ_X
static const size_t O_XLO  = O_XHI  + SZ_X * 2;
static const size_t O_WHI  = O_XLO  + SZ_X * 2;               // bf16 3*DIM*DIM
static const size_t O_WLO  = O_WHI  + (size_t)3 * DIM * DIM * 2;
static const size_t O_QKV  = O_WLO  + (size_t)3 * DIM * DIM * 2;   // fp32 3*SZ_X
static const size_t O_QKHI = O_QKV  + (size_t)3 * SZ_X * 4;   // bf16 2*SZ_X
static const size_t O_QKLO = O_QKHI + (size_t)2 * SZ_X * 2;
static const size_t O_VTHI = O_QKLO + (size_t)2 * SZ_X * 2;   // bf16 SZ_X (V^T)
static const size_t O_VTLO = O_VTHI + SZ_X * 2;
static const size_t O_S    = O_VTLO + SZ_X * 2;               // fp32 B*S*S
static const size_t O_SHI  = O_S    + (size_t)BATCH * SEQ * SEQ * 4;
static const size_t O_SLO  = O_SHI  + (size_t)BATCH * SEQ * SEQ * 2;
static const size_t SCRATCH_TOTAL = O_SLO + (size_t)BATCH * SEQ * SEQ * 2;

__device__ __align__(1024) unsigned char g_scratch[SCRATCH_TOTAL];

// ===========================================================================
// PTX helpers (arch-agnostic only: cp.async / ldmatrix / mma.sync)
// ===========================================================================
__device__ __forceinline__ uint32_t smem_u32(const void* p) {
    uint32_t a;
    asm("{ .reg .u64 t; cvta.to.shared.u64 t, %1; cvt.u32.u64 %0, t; }"
        : "=r"(a) : "l"(p));
    return a;
}

#define SWZ128(x) ((x) ^ (((x) >> 3) & 0x70))

__device__ __forceinline__ void cp16(uint32_t dst, const void* src) {
    asm volatile("cp.async.cg.shared.global [%0], [%1], 16;\n"
                 :: "r"(dst), "l"(src));
}
__device__ __forceinline__ void cp_commit() {
    asm volatile("cp.async.commit_group;\n" ::: "memory");
}
template <int N> __device__ __forceinline__ void cp_wait() {
    asm volatile("cp.async.wait_group %0;\n" :: "n"(N) : "memory");
}

__device__ __forceinline__ void ldm_x4(uint32_t* r, uint32_t addr) {
    asm volatile("ldmatrix.sync.aligned.m8n8.x4.shared.b16 {%0,%1,%2,%3}, [%4];"
                 : "=r"(r[0]), "=r"(r[1]), "=r"(r[2]), "=r"(r[3]) : "r"(addr));
}

__device__ __forceinline__ void mma_bf16(float* c, const uint32_t* a,
                                         uint32_t b0, uint32_t b1) {
    asm volatile("mma.sync.aligned.m16n8k16.row.col.f32.bf16.bf16.f32 "
                 "{%0,%1,%2,%3}, {%4,%5,%6,%7}, {%8,%9}, {%0,%1,%2,%3};"
                 : "+f"(c[0]), "+f"(c[1]), "+f"(c[2]), "+f"(c[3])
                 : "r"(a[0]), "r"(a[1]), "r"(a[2]), "r"(a[3]), "r"(b0), "r"(b1));
}

// ===========================================================================
// HMMA GEMM:  C[M,N] (fp32 * alpha) = A0@B0^T + A1@B0^T + A0@B1^T   (bf16 NT)
// CTA 128x128, BK=64, cp.async double buffer, 8 warps x (32M x 64N) tiles.
// ===========================================================================
#define SMEM_GEMM (65536 + 1024)

__global__ __launch_bounds__(256, 1)
void hgemm_nt_x3(const __nv_bfloat16* __restrict__ A0,
                 const __nv_bfloat16* __restrict__ A1,
                 const __nv_bfloat16* __restrict__ B0,
                 const __nv_bfloat16* __restrict__ B1,
                 float* __restrict__ C,
                 int ldA, int ldB, int ldC, int kTiles,
                 size_t sA, size_t sB, size_t sC, float alpha)
{
    extern __shared__ char smem_raw[];
    const uint32_t sbase = (smem_u32(smem_raw) + 1023u) & ~1023u;

    const int tid  = threadIdx.x;
    const int wid  = tid >> 5;
    const int lane = tid & 31;
    const int wm   = wid & 3;      // 4 M-warps -> 32 rows each
    const int wn   = wid >> 2;     // 2 N-warps -> 64 cols each

    const int row0 = blockIdx.y * 128;
    const int col0 = blockIdx.x * 128;

    A0 += (size_t)blockIdx.z * sA;  A1 += (size_t)blockIdx.z * sA;
    B0 += (size_t)blockIdx.z * sB;  B1 += (size_t)blockIdx.z * sB;
    C  += (size_t)blockIdx.z * sC;

    const int S = 3 * kTiles;

    float acc[2][8][4];
    #pragma unroll
    for (int mt = 0; mt < 2; mt++)
        #pragma unroll
        for (int j = 0; j < 8; j++)
            #pragma unroll
            for (int q = 0; q < 4; q++) acc[mt][j][q] = 0.f;

    // loader: 128 rows x 8 chunks of 16B for each of A,B => 4 cp16/thread each
    const int l_r = tid >> 1;            // used twice per iter pattern below
    (void)l_r;

    auto load_stage = [&](int s) {
        const int term = s / kTiles;
        const int kk   = (s - term * kTiles) * 64;
        const __nv_bfloat16* A = (term == 1) ? A1 : A0;
        const __nv_bfloat16* B = (term == 2) ? B1 : B0;
        const uint32_t off = (uint32_t)(s & 1) * 32768u;
        const uint32_t sA_ = sbase + off;
        const uint32_t sB_ = sbase + off + 16384u;
        #pragma unroll
        for (int i = 0; i < 4; i++) {
            int idx = tid + i * 256;
            int r = idx >> 3, c = idx & 7;
            cp16(sA_ + SWZ128((uint32_t)(r * 128 + c * 16)),
                 A + (size_t)(row0 + r) * ldA + kk + c * 8);
        }
        #pragma unroll
        for (int i = 0; i < 4; i++) {
            int idx = tid + i * 256;
            int r = idx >> 3, c = idx & 7;
            cp16(sB_ + SWZ128((uint32_t)(r * 128 + c * 16)),
                 B + (size_t)(col0 + r) * ldB + kk + c * 8);
        }
        cp_commit();
    };

    load_stage(0);

    for (int s = 0; s < S; s++) {
        if (s + 1 < S) {
            load_stage(s + 1);
            cp_wait<1>();
        } else {
            cp_wait<0>();
        }
        __syncthreads();

        const uint32_t As = sbase + (uint32_t)(s & 1) * 32768u;
        const uint32_t Bs = As + 16384u;
        const uint32_t lrow = (uint32_t)(lane & 15);
        const uint32_t lcol = (uint32_t)((lane >> 4) * 16);

        #pragma unroll
        for (int k16 = 0; k16 < 4; k16++) {
            uint32_t a[2][4];
            #pragma unroll
            for (int mt = 0; mt < 2; mt++)
                ldm_x4(a[mt], As + SWZ128((uint32_t)((wm * 32 + mt * 16 + lrow) * 128)
                                          + (uint32_t)(k16 * 32) + lcol));
            uint32_t b[4][4];
            #pragma unroll
            for (int ng = 0; ng < 4; ng++)
                ldm_x4(b[ng], Bs + SWZ128((uint32_t)((wn * 64 + ng * 16 + lrow) * 128)
                                          + (uint32_t)(k16 * 32) + lcol));
            #pragma unroll
            for (int mt = 0; mt < 2; mt++)
                #pragma unroll
                for (int j = 0; j < 8; j++) {
                    int ng = j >> 1, hi = j & 1;
                    mma_bf16(acc[mt][j], a[mt], b[ng][hi ? 1 : 0], b[ng][hi ? 3 : 2]);
                }
        }
        __syncthreads();   // all warps done with buf before it is reloaded
    }

    // Epilogue: fragment (t/4 -> row, 2*(t%4) -> col pair)
    const int er = lane >> 2;
    const int ec = (lane & 3) * 2;
    #pragma unroll
    for (int mt = 0; mt < 2; mt++) {
        const int rb = row0 + wm * 32 + mt * 16 + er;
        #pragma unroll
        for (int j = 0; j < 8; j++) {
            const int cb = col0 + wn * 64 + j * 8 + ec;
            float2 v0 = make_float2(alpha * acc[mt][j][0], alpha * acc[mt][j][1]);
            float2 v1 = make_float2(alpha * acc[mt][j][2], alpha * acc[mt][j][3]);
            *(float2*)(C + (size_t)rb * ldC + cb)       = v0;
            *(float2*)(C + (size_t)(rb + 8) * ldC + cb) = v1;
        }
    }
}

// ===========================================================================
// fp32 -> (bf16 hi, bf16 lo) elementwise split, 4 elems/thread
// ===========================================================================
__global__ __launch_bounds__(256)
void split2(const float* __restrict__ src, __nv_bfloat16* __restrict__ hi,
            __nv_bfloat16* __restrict__ lo, size_t n4)
{
    size_t i = (size_t)blockIdx.x * 256 + threadIdx.x;
    if (i >= n4) return;
    float4 v = ((const float4*)src)[i];
    __nv_bfloat16 h0 = __float2bfloat16(v.x);
    __nv_bfloat16 h1 = __float2bfloat16(v.y);
    __nv_bfloat16 h2 = __float2bfloat16(v.z);
    __nv_bfloat16 h3 = __float2bfloat16(v.w);
    __nv_bfloat162 H0; H0.x = h0; H0.y = h1;
    __nv_bfloat162 H1; H1.x = h2; H1.y = h3;
    ((__nv_bfloat162*)hi)[2 * i + 0] = H0;
    ((__nv_bfloat162*)hi)[2 * i + 1] = H1;
    __nv_bfloat162 L0, L1;
    L0.x = __float2bfloat16(v.x - __bfloat162float(h0));
    L0.y = __float2bfloat16(v.y - __bfloat162float(h1));
    L1.x = __float2bfloat16(v.z - __bfloat162float(h2));
    L1.y = __float2bfloat16(v.w - __bfloat162float(h3));
    ((__nv_bfloat162*)lo)[2 * i + 0] = L0;
    ((__nv_bfloat162*)lo)[2 * i + 1] = L1;
}

// ===========================================================================
// V [b,s,d] fp32 -> V^T [b,d,s] split into bf16 hi/lo (32x32 smem transpose)
// ===========================================================================
__global__ __launch_bounds__(256)
void splitT_V(const float* __restrict__ V, __nv_bfloat16* __restrict__ hi,
              __nv_bfloat16* __restrict__ lo)
{
    __shared__ float t[32][33];
    const int b  = blockIdx.z;
    const int s0 = blockIdx.x * 32, d0 = blockIdx.y * 32;
    const int tx = threadIdx.x, ty = threadIdx.y;   // block (32, 8)
    const float* Vb = V + (size_t)b * SEQ * DIM;
    #pragma unroll
    for (int i = ty; i < 32; i += 8)
        t[i][tx] = Vb[(size_t)(s0 + i) * DIM + d0 + tx];
    __syncthreads();
    __nv_bfloat16* Hb = hi + (size_t)b * DIM * SEQ;
    __nv_bfloat16* Lb = lo + (size_t)b * DIM * SEQ;
    #pragma unroll
    for (int i = ty; i < 32; i += 8) {
        float v = t[tx][i];                         // = V[s0+tx][d0+i]
        __nv_bfloat16 h = __float2bfloat16(v);
        size_t o = (size_t)(d0 + i) * SEQ + s0 + tx;
        Hb[o] = h;
        Lb[o] = __float2bfloat16(v - __bfloat162float(h));
    }
}

// ===========================================================================
// Row softmax fused with bf16 hi/lo split output
// ===========================================================================
__global__ __launch_bounds__(256)
void softmax_split(const float* __restrict__ S, __nv_bfloat16* __restrict__ hi,
                   __nv_bfloat16* __restrict__ lo)
{
    __shared__ float row[SEQ];
    __shared__ float red[256];
    const size_t base = (size_t)blockIdx.x * SEQ;
    const int tid = threadIdx.x;

    float m = -1e30f;
    for (int i = tid; i < SEQ; i += 256) {
        float v = S[base + i];
        row[i] = v;
        m = fmaxf(m, v);
    }
    red[tid] = m;
    __syncthreads();
    #pragma unroll
    for (int s = 128; s > 0; s >>= 1) {
        if (tid < s) red[tid] = fmaxf(red[tid], red[tid + s]);
        __syncthreads();
    }
    m = red[0];
    __syncthreads();

    float sum = 0.f;
    for (int i = tid; i < SEQ; i += 256) {
        float e = __expf(row[i] - m);
        row[i] = e;
        sum += e;
    }
    red[tid] = sum;
    __syncthreads();
    #pragma unroll
    for (int s = 128; s > 0; s >>= 1) {
        if (tid < s) red[tid] += red[tid + s];
        __syncthreads();
    }
    const float inv = 1.f / red[0];
    __syncthreads();

    for (int i = tid; i < SEQ; i += 256) {
        float a = row[i] * inv;
        __nv_bfloat16 h = __float2bfloat16(a);
        hi[base + i] = h;
        lo[base + i] = __float2bfloat16(a - __bfloat162float(h));
    }
}

// ===========================================================================
extern "C" void kernel_launch(void* const* d_in, const int* in_sizes, int n_in,
                              void* d_out, int out_size)
{
    const float* x  = (const float*)d_in[0];
    const float* Wq = (const float*)d_in[1];
    const float* Wk = (const float*)d_in[2];
    const float* Wv = (const float*)d_in[3];
    float* out = (float*)d_out;

    cudaFuncSetAttribute(hgemm_nt_x3, cudaFuncAttributeMaxDynamicSharedMemorySize,
                         SMEM_GEMM);

    unsigned char* base;
    cudaGetSymbolAddress((void**)&base, g_scratch);

    __nv_bfloat16* xhi  = (__nv_bfloat16*)(base + O_XHI);
    __nv_bfloat16* xlo  = (__nv_bfloat16*)(base + O_XLO);
    __nv_bfloat16* whi  = (__nv_bfloat16*)(base + O_WHI);
    __nv_bfloat16* wlo  = (__nv_bfloat16*)(base + O_WLO);
    float*         qkv  = (float*)(base + O_QKV);
    __nv_bfloat16* qkhi = (__nv_bfloat16*)(base + O_QKHI);
    __nv_bfloat16* qklo = (__nv_bfloat16*)(base + O_QKLO);
    __nv_bfloat16* vthi = (__nv_bfloat16*)(base + O_VTHI);
    __nv_bfloat16* vtlo = (__nv_bfloat16*)(base + O_VTLO);
    float*         Sf   = (float*)(base + O_S);
    __nv_bfloat16* shi  = (__nv_bfloat16*)(base + O_SHI);
    __nv_bfloat16* slo  = (__nv_bfloat16*)(base + O_SLO);

    const float scale = 0.044194173824159216f;   // 1/sqrt(512)

    // 1. split x and the three weight matrices
    split2<<<(unsigned)(SZ_X / 4 / 256), 256>>>(x, xhi, xlo, SZ_X / 4);
    split2<<<DIM * DIM / 4 / 256, 256>>>(Wq, whi,                 wlo,                 DIM * DIM / 4);
    split2<<<DIM * DIM / 4 / 256, 256>>>(Wk, whi + DIM * DIM,     wlo + DIM * DIM,     DIM * DIM / 4);
    split2<<<DIM * DIM / 4 / 256, 256>>>(Wv, whi + 2 * DIM * DIM, wlo + 2 * DIM * DIM, DIM * DIM / 4);

    // 2. QKV projections (grid.z batches the 3 weight matrices)
    {
        dim3 g(DIM / 128, MTOT / 128, 3);
        hgemm_nt_x3<<<g, 256, SMEM_GEMM>>>(xhi, xlo, whi, wlo, qkv,
                                           DIM, DIM, DIM, DIM / 64,
                                           0, (size_t)DIM * DIM, SZ_X, 1.0f);
    }

    // 3. split Q,K (contiguous) + transpose-split V
    split2<<<(unsigned)(2 * SZ_X / 4 / 256), 256>>>(qkv, qkhi, qklo, 2 * SZ_X / 4);
    {
        dim3 g(SEQ / 32, DIM / 32, BATCH), b(32, 8);
        splitT_V<<<g, b>>>(qkv + 2 * SZ_X, vthi, vtlo);
    }

    // 4. scores = Q @ K^T * scale
    {
        __nv_bfloat16* qhi = qkhi;         __nv_bfloat16* qlo = qklo;
        __nv_bfloat16* khi = qkhi + SZ_X;  __nv_bfloat16* klo = qklo + SZ_X;
        dim3 g(SEQ / 128, SEQ / 128, BATCH);
        hgemm_nt_x3<<<g, 256, SMEM_GEMM>>>(qhi, qlo, khi, klo, Sf,
                                           DIM, DIM, SEQ, DIM / 64,
                                           (size_t)SEQ * DIM, (size_t)SEQ * DIM,
                                           (size_t)SEQ * SEQ, scale);
    }

    // 5. softmax + split
    softmax_split<<<BATCH * SEQ, 256>>>(Sf, shi, slo);

    // 6. out = attn @ V  (V pre-transposed -> NT form)
    {
        dim3 g(DIM / 128, SEQ / 128, BATCH);
        hgemm_nt_x3<<<g, 256, SMEM_GEMM>>>(shi, slo, vthi, vtlo, out,
                                           SEQ, SEQ, DIM, SEQ / 64,
                                           (size_t)SEQ * SEQ, (size_t)DIM * SEQ,
                                           (size_t)SEQ * DIM, 1.0f);
    }
}

// round 4
// speedup vs baseline: 2.9110x; 1.2811x over previous
#include <cuda_runtime.h>
#include <cuda_bf16.h>
#include <math.h>
#include <stdint.h>

#define BATCH 8
#define SEQ   2048
#define DIM   512
#define MTOT  (BATCH*SEQ)        // 16384

// ===========================================================================
// Scratch memory (single __device__ array; no allocation anywhere)
// ===========================================================================
#define SZ_X ((size_t)MTOT * DIM)                     // 8,388,608 elems
static const size_t O_XHI   = 0;                                // bf16 SZ_X
static const size_t O_XLO   = O_XHI   + SZ_X * 2;
static const size_t O_WHI   = O_XLO   + SZ_X * 2;               // bf16 3*DIM*DIM
static const size_t O_WLO   = O_WHI   + (size_t)3 * DIM * DIM * 2;
static const size_t O_QKVHI = O_WLO   + (size_t)3 * DIM * DIM * 2;  // bf16 3*SZ_X (Q,K,V)
static const size_t O_QKVLO = O_QKVHI + (size_t)3 * SZ_X * 2;
static const size_t O_VTHI  = O_QKVLO + (size_t)3 * SZ_X * 2;   // bf16 SZ_X (V^T)
static const size_t O_VTLO  = O_VTHI  + SZ_X * 2;
static const size_t O_S     = O_VTLO  + SZ_X * 2;               // fp32 B*S*S
static const size_t O_SHI   = O_S     + (size_t)BATCH * SEQ * SEQ * 4;
static const size_t O_SLO   = O_SHI   + (size_t)BATCH * SEQ * SEQ * 2;
static const size_t SCRATCH_TOTAL = O_SLO + (size_t)BATCH * SEQ * SEQ * 2;

__device__ __align__(1024) unsigned char g_scratch[SCRATCH_TOTAL];

// ===========================================================================
// PTX helpers (arch-agnostic: cp.async / ldmatrix / mma.sync only)
// ===========================================================================
__device__ __forceinline__ uint32_t smem_u32(const void* p) {
    uint32_t a;
    asm("{ .reg .u64 t; cvta.to.shared.u64 t, %1; cvt.u32.u64 %0, t; }"
        : "=r"(a) : "l"(p));
    return a;
}

#define SWZ128(x) ((x) ^ (((x) >> 3) & 0x70))

__device__ __forceinline__ void cp16(uint32_t dst, const void* src) {
    asm volatile("cp.async.cg.shared.global [%0], [%1], 16;\n"
                 :: "r"(dst), "l"(src));
}
__device__ __forceinline__ void cp_commit() {
    asm volatile("cp.async.commit_group;\n" ::: "memory");
}
template <int N> __device__ __forceinline__ void cp_wait() {
    asm volatile("cp.async.wait_group %0;\n" :: "n"(N) : "memory");
}

__device__ __forceinline__ void ldm_x4(uint32_t* r, uint32_t addr) {
    asm volatile("ldmatrix.sync.aligned.m8n8.x4.shared.b16 {%0,%1,%2,%3}, [%4];"
                 : "=r"(r[0]), "=r"(r[1]), "=r"(r[2]), "=r"(r[3]) : "r"(addr));
}

__device__ __forceinline__ void mma_bf16(float* c, const uint32_t* a,
                                         uint32_t b0, uint32_t b1) {
    asm volatile("mma.sync.aligned.m16n8k16.row.col.f32.bf16.bf16.f32 "
                 "{%0,%1,%2,%3}, {%4,%5,%6,%7}, {%8,%9}, {%0,%1,%2,%3};"
                 : "+f"(c[0]), "+f"(c[1]), "+f"(c[2]), "+f"(c[3])
                 : "r"(a[0]), "r"(a[1]), "r"(a[2]), "r"(a[3]), "r"(b0), "r"(b1));
}

// ===========================================================================
// HMMA GEMM:  C[M,N] = alpha * (Ahi@Bhi^T + Alo@Bhi^T + Ahi@Blo^T)   (bf16 NT)
// All four operand tiles loaded per k-stage (shared across the 3 products).
// CTA 128x128, BK=64, double-buffered cp.async, 8 warps x (32M x 64N).
// Epilogue: fp32*alpha if Chi==null, else bf16 hi/lo split (alpha ignored).
// ===========================================================================
#define SMEM_GEMM (131072 + 1024)

__global__ __launch_bounds__(256, 1)
void hgemm3(const __nv_bfloat16* __restrict__ Ahi,
            const __nv_bfloat16* __restrict__ Alo,
            const __nv_bfloat16* __restrict__ Bhi,
            const __nv_bfloat16* __restrict__ Blo,
            float* __restrict__ C,
            __nv_bfloat16* __restrict__ Chi,
            __nv_bfloat16* __restrict__ Clo,
            int ldA, int ldB, int ldC, int kTiles,
            size_t sA, size_t sB, size_t sC, float alpha)
{
    extern __shared__ char smem_raw[];
    const uint32_t sbase = (smem_u32(smem_raw) + 1023u) & ~1023u;

    const int tid  = threadIdx.x;
    const int wid  = tid >> 5;
    const int lane = tid & 31;
    const int wm   = wid & 3;      // 4 M-warps -> 32 rows each
    const int wn   = wid >> 2;     // 2 N-warps -> 64 cols each

    const int row0 = blockIdx.y * 128;
    const int col0 = blockIdx.x * 128;

    Ahi += (size_t)blockIdx.z * sA;  Alo += (size_t)blockIdx.z * sA;
    Bhi += (size_t)blockIdx.z * sB;  Blo += (size_t)blockIdx.z * sB;

    float acc[2][8][4];
    #pragma unroll
    for (int mt = 0; mt < 2; mt++)
        #pragma unroll
        for (int j = 0; j < 8; j++)
            #pragma unroll
            for (int q = 0; q < 4; q++) acc[mt][j][q] = 0.f;

    // stage buffer: [A_hi 16K][A_lo 16K][B_hi 16K][B_lo 16K], x2 stages
    auto load_stage = [&](int t) {
        const int kk = t * 64;
        const uint32_t st = sbase + (uint32_t)(t & 1) * 65536u;
        const int r = tid >> 3, c = tid & 7;          // 128 rows x 8 chunks of 16B
        const uint32_t dA = SWZ128((uint32_t)(r * 128 + c * 16));
        const size_t   oA = (size_t)(row0 + r) * ldA + kk + c * 8;
        const size_t   oB = (size_t)(col0 + r) * ldB + kk + c * 8;
        #pragma unroll
        for (int q = 0; q < 4; q++) {
            int idx = tid + q * 256;
            int rr = idx >> 3, cc = idx & 7;
            uint32_t d = SWZ128((uint32_t)(rr * 128 + cc * 16));
            size_t oa = (size_t)(row0 + rr) * ldA + kk + cc * 8;
            size_t ob = (size_t)(col0 + rr) * ldB + kk + cc * 8;
            cp16(st +          d, Ahi + oa);
            cp16(st + 16384u + d, Alo + oa);
            cp16(st + 32768u + d, Bhi + ob);
            cp16(st + 49152u + d, Blo + ob);
        }
        (void)dA; (void)oA; (void)oB;
        cp_commit();
    };

    load_stage(0);

    const uint32_t lrow = (uint32_t)(lane & 15);
    const uint32_t lcol = (uint32_t)((lane >> 4) * 16);

    for (int t = 0; t < kTiles; t++) {
        if (t + 1 < kTiles) {
            load_stage(t + 1);
            cp_wait<1>();
        } else {
            cp_wait<0>();
        }
        __syncthreads();

        const uint32_t st  = sbase + (uint32_t)(t & 1) * 65536u;
        const uint32_t Ahs = st;
        const uint32_t Als = st + 16384u;
        const uint32_t Bhs = st + 32768u;
        const uint32_t Bls = st + 49152u;

        #pragma unroll
        for (int k16 = 0; k16 < 4; k16++) {
            const uint32_t koff = (uint32_t)(k16 * 32) + lcol;
            uint32_t ah[2][4], al[2][4];
            #pragma unroll
            for (int mt = 0; mt < 2; mt++) {
                uint32_t ro = SWZ128((uint32_t)((wm * 32 + mt * 16 + lrow) * 128) + koff);
                ldm_x4(ah[mt], Ahs + ro);
                ldm_x4(al[mt], Als + ro);
            }
            uint32_t bh[4][4], bl[4][4];
            #pragma unroll
            for (int ng = 0; ng < 4; ng++) {
                uint32_t ro = SWZ128((uint32_t)((wn * 64 + ng * 16 + lrow) * 128) + koff);
                ldm_x4(bh[ng], Bhs + ro);
                ldm_x4(bl[ng], Bls + ro);
            }
            #pragma unroll
            for (int mt = 0; mt < 2; mt++)
                #pragma unroll
                for (int j = 0; j < 8; j++) {
                    const int ng = j >> 1;
                    const int b0 = (j & 1) ? 1 : 0, b1 = (j & 1) ? 3 : 2;
                    mma_bf16(acc[mt][j], ah[mt], bh[ng][b0], bh[ng][b1]);
                    mma_bf16(acc[mt][j], al[mt], bh[ng][b0], bh[ng][b1]);
                    mma_bf16(acc[mt][j], ah[mt], bl[ng][b0], bl[ng][b1]);
                }
        }
        __syncthreads();
    }

    // Epilogue
    const int er = lane >> 2;
    const int ec = (lane & 3) * 2;
    if (Chi) {
        Chi += (size_t)blockIdx.z * sC;
        Clo += (size_t)blockIdx.z * sC;
        #pragma unroll
        for (int mt = 0; mt < 2; mt++) {
            const int rb = row0 + wm * 32 + mt * 16 + er;
            #pragma unroll
            for (int j = 0; j < 8; j++) {
                const int cb = col0 + wn * 64 + j * 8 + ec;
                #pragma unroll
                for (int h = 0; h < 2; h++) {
                    float vx = acc[mt][j][2 * h + 0];
                    float vy = acc[mt][j][2 * h + 1];
                    __nv_bfloat162 H, L;
                    H.x = __float2bfloat16(vx);
                    H.y = __float2bfloat16(vy);
                    L.x = __float2bfloat16(vx - __bfloat162float(H.x));
                    L.y = __float2bfloat16(vy - __bfloat162float(H.y));
                    const size_t o = (size_t)(rb + 8 * h) * ldC + cb;
                    *(__nv_bfloat162*)(Chi + o) = H;
                    *(__nv_bfloat162*)(Clo + o) = L;
                }
            }
        }
    } else {
        C += (size_t)blockIdx.z * sC;
        #pragma unroll
        for (int mt = 0; mt < 2; mt++) {
            const int rb = row0 + wm * 32 + mt * 16 + er;
            #pragma unroll
            for (int j = 0; j < 8; j++) {
                const int cb = col0 + wn * 64 + j * 8 + ec;
                float2 v0 = make_float2(alpha * acc[mt][j][0], alpha * acc[mt][j][1]);
                float2 v1 = make_float2(alpha * acc[mt][j][2], alpha * acc[mt][j][3]);
                *(float2*)(C + (size_t)rb * ldC + cb)       = v0;
                *(float2*)(C + (size_t)(rb + 8) * ldC + cb) = v1;
            }
        }
    }
}

// ===========================================================================
// fp32 -> (bf16 hi, bf16 lo) elementwise split, 4 elems/thread
// ===========================================================================
__global__ __launch_bounds__(256)
void split2(const float* __restrict__ src, __nv_bfloat16* __restrict__ hi,
            __nv_bfloat16* __restrict__ lo, size_t n4)
{
    size_t i = (size_t)blockIdx.x * 256 + threadIdx.x;
    if (i >= n4) return;
    float4 v = ((const float4*)src)[i];
    __nv_bfloat16 h0 = __float2bfloat16(v.x);
    __nv_bfloat16 h1 = __float2bfloat16(v.y);
    __nv_bfloat16 h2 = __float2bfloat16(v.z);
    __nv_bfloat16 h3 = __float2bfloat16(v.w);
    __nv_bfloat162 H0; H0.x = h0; H0.y = h1;
    __nv_bfloat162 H1; H1.x = h2; H1.y = h3;
    ((__nv_bfloat162*)hi)[2 * i + 0] = H0;
    ((__nv_bfloat162*)hi)[2 * i + 1] = H1;
    __nv_bfloat162 L0, L1;
    L0.x = __float2bfloat16(v.x - __bfloat162float(h0));
    L0.y = __float2bfloat16(v.y - __bfloat162float(h1));
    L1.x = __float2bfloat16(v.z - __bfloat162float(h2));
    L1.y = __float2bfloat16(v.w - __bfloat162float(h3));
    ((__nv_bfloat162*)lo)[2 * i + 0] = L0;
    ((__nv_bfloat162*)lo)[2 * i + 1] = L1;
}

// ===========================================================================
// bf16 [b,s,d] -> bf16 [b,d,s] transpose (64x64 tiles). grid.z = batch*2
// selects hi (z even) or lo (z odd) tensor pair.
// ===========================================================================
__global__ __launch_bounds__(256)
void transpose_bf16(const __nv_bfloat16* __restrict__ srcHi,
                    __nv_bfloat16* __restrict__ dstHi,
                    const __nv_bfloat16* __restrict__ srcLo,
                    __nv_bfloat16* __restrict__ dstLo)
{
    __shared__ __nv_bfloat16 t[64][65];
    const int z = blockIdx.z;
    const int b = z >> 1;
    const __nv_bfloat16* src = (z & 1) ? srcLo : srcHi;
    __nv_bfloat16*       dst = (z & 1) ? dstLo : dstHi;
    const int s0 = blockIdx.x * 64, d0 = blockIdx.y * 64;
    const int tid = threadIdx.x;
    src += (size_t)b * SEQ * DIM;
    dst += (size_t)b * DIM * SEQ;

    #pragma unroll
    for (int q = 0; q < 8; q++) {
        int i = tid + q * 256;
        int row = i >> 5, cp = i & 31;
        __nv_bfloat162 v = *(const __nv_bfloat162*)
            (src + (size_t)(s0 + row) * DIM + d0 + cp * 2);
        t[row][cp * 2 + 0] = v.x;
        t[row][cp * 2 + 1] = v.y;
    }
    __syncthreads();
    #pragma unroll
    for (int q = 0; q < 8; q++) {
        int i = tid + q * 256;
        int drow = i >> 5, sp = i & 31;
        __nv_bfloat162 o;
        o.x = t[sp * 2 + 0][drow];
        o.y = t[sp * 2 + 1][drow];
        *(__nv_bfloat162*)(dst + (size_t)(d0 + drow) * SEQ + s0 + sp * 2) = o;
    }
}

// ===========================================================================
// Row softmax (row held in registers) fused with bf16 hi/lo split output
// ===========================================================================
__global__ __launch_bounds__(256)
void softmax_split(const float* __restrict__ S, __nv_bfloat16* __restrict__ hi,
                   __nv_bfloat16* __restrict__ lo)
{
    __shared__ float red_m[8];
    __shared__ float red_s[8];
    const size_t base = (size_t)blockIdx.x * SEQ;
    const int tid  = threadIdx.x;
    const int wid  = tid >> 5;
    const int lane = tid & 31;

    const float4* row4 = (const float4*)(S + base);
    float4 v0 = row4[tid];
    float4 v1 = row4[tid + 256];

    float m = fmaxf(fmaxf(fmaxf(v0.x, v0.y), fmaxf(v0.z, v0.w)),
                    fmaxf(fmaxf(v1.x, v1.y), fmaxf(v1.z, v1.w)));
    #pragma unroll
    for (int o = 16; o > 0; o >>= 1) m = fmaxf(m, __shfl_xor_sync(~0u, m, o));
    if (lane == 0) red_m[wid] = m;
    __syncthreads();
    m = red_m[0];
    #pragma unroll
    for (int i = 1; i < 8; i++) m = fmaxf(m, red_m[i]);

    v0.x = __expf(v0.x - m); v0.y = __expf(v0.y - m);
    v0.z = __expf(v0.z - m); v0.w = __expf(v0.w - m);
    v1.x = __expf(v1.x - m); v1.y = __expf(v1.y - m);
    v1.z = __expf(v1.z - m); v1.w = __expf(v1.w - m);

    float s = v0.x + v0.y + v0.z + v0.w + v1.x + v1.y + v1.z + v1.w;
    #pragma unroll
    for (int o = 16; o > 0; o >>= 1) s += __shfl_xor_sync(~0u, s, o);
    if (lane == 0) red_s[wid] = s;
    __syncthreads();
    s = red_s[0];
    #pragma unroll
    for (int i = 1; i < 8; i++) s += red_s[i];
    const float inv = 1.f / s;

    auto emit = [&](float4 v, int c0) {
        float a0 = v.x * inv, a1 = v.y * inv, a2 = v.z * inv, a3 = v.w * inv;
        __nv_bfloat162 H0, H1, L0, L1;
        H0.x = __float2bfloat16(a0); H0.y = __float2bfloat16(a1);
        H1.x = __float2bfloat16(a2); H1.y = __float2bfloat16(a3);
        L0.x = __float2bfloat16(a0 - __bfloat162float(H0.x));
        L0.y = __float2bfloat16(a1 - __bfloat162float(H0.y));
        L1.x = __float2bfloat16(a2 - __bfloat162float(H1.x));
        L1.y = __float2bfloat16(a3 - __bfloat162float(H1.y));
        *(__nv_bfloat162*)(hi + base + c0)     = H0;
        *(__nv_bfloat162*)(hi + base + c0 + 2) = H1;
        *(__nv_bfloat162*)(lo + base + c0)     = L0;
        *(__nv_bfloat162*)(lo + base + c0 + 2) = L1;
    };
    emit(v0, tid * 4);
    emit(v1, (tid + 256) * 4);
}

// ===========================================================================
extern "C" void kernel_launch(void* const* d_in, const int* in_sizes, int n_in,
                              void* d_out, int out_size)
{
    const float* x  = (const float*)d_in[0];
    const float* Wq = (const float*)d_in[1];
    const float* Wk = (const float*)d_in[2];
    const float* Wv = (const float*)d_in[3];
    float* out = (float*)d_out;

    cudaFuncSetAttribute(hgemm3, cudaFuncAttributeMaxDynamicSharedMemorySize,
                         SMEM_GEMM);

    unsigned char* base;
    cudaGetSymbolAddress((void**)&base, g_scratch);

    __nv_bfloat16* xhi   = (__nv_bfloat16*)(base + O_XHI);
    __nv_bfloat16* xlo   = (__nv_bfloat16*)(base + O_XLO);
    __nv_bfloat16* whi   = (__nv_bfloat16*)(base + O_WHI);
    __nv_bfloat16* wlo   = (__nv_bfloat16*)(base + O_WLO);
    __nv_bfloat16* qkvhi = (__nv_bfloat16*)(base + O_QKVHI);
    __nv_bfloat16* qkvlo = (__nv_bfloat16*)(base + O_QKVLO);
    __nv_bfloat16* vthi  = (__nv_bfloat16*)(base + O_VTHI);
    __nv_bfloat16* vtlo  = (__nv_bfloat16*)(base + O_VTLO);
    float*         Sf    = (float*)(base + O_S);
    __nv_bfloat16* shi   = (__nv_bfloat16*)(base + O_SHI);
    __nv_bfloat16* slo   = (__nv_bfloat16*)(base + O_SLO);

    const float scale = 0.044194173824159216f;   // 1/sqrt(512)

    // 1. split x and the three weight matrices
    split2<<<(unsigned)(SZ_X / 4 / 256), 256>>>(x, xhi, xlo, SZ_X / 4);
    split2<<<DIM * DIM / 4 / 256, 256>>>(Wq, whi,                 wlo,                 DIM * DIM / 4);
    split2<<<DIM * DIM / 4 / 256, 256>>>(Wk, whi + DIM * DIM,     wlo + DIM * DIM,     DIM * DIM / 4);
    split2<<<DIM * DIM / 4 / 256, 256>>>(Wv, whi + 2 * DIM * DIM, wlo + 2 * DIM * DIM, DIM * DIM / 4);

    // 2. QKV projections, split bf16 epilogue (grid.z batches the 3 weights)
    {
        dim3 g(DIM / 128, MTOT / 128, 3);
        hgemm3<<<g, 256, SMEM_GEMM>>>(xhi, xlo, whi, wlo,
                                      nullptr, qkvhi, qkvlo,
                                      DIM, DIM, DIM, DIM / 64,
                                      0, (size_t)DIM * DIM, SZ_X, 1.0f);
    }

    // 3. transpose V (hi and lo) -> V^T
    {
        dim3 g(SEQ / 64, DIM / 64, BATCH * 2);
        transpose_bf16<<<g, 256>>>(qkvhi + 2 * SZ_X, vthi, qkvlo + 2 * SZ_X, vtlo);
    }

    // 4. scores = Q @ K^T * scale  (fp32 epilogue)
    {
        dim3 g(SEQ / 128, SEQ / 128, BATCH);
        hgemm3<<<g, 256, SMEM_GEMM>>>(qkvhi, qkvlo, qkvhi + SZ_X, qkvlo + SZ_X,
                                      Sf, nullptr, nullptr,
                                      DIM, DIM, SEQ, DIM / 64,
                                      (size_t)SEQ * DIM, (size_t)SEQ * DIM,
                                      (size_t)SEQ * SEQ, scale);
    }

    // 5. softmax + split
    softmax_split<<<BATCH * SEQ, 256>>>(Sf, shi, slo);

    // 6. out = attn @ V  (V pre-transposed -> NT form, fp32 epilogue)
    {
        dim3 g(DIM / 128, SEQ / 128, BATCH);
        hgemm3<<<g, 256, SMEM_GEMM>>>(shi, slo, vthi, vtlo,
                                      out, nullptr, nullptr,
                                      SEQ, SEQ, DIM, SEQ / 64,
                                      (size_t)SEQ * SEQ, (size_t)DIM * SEQ,
                                      (size_t)SEQ * DIM, 1.0f);
    }
}

// round 5
// speedup vs baseline: 2.9315x; 1.0071x over previous
#include <cuda_runtime.h>
#include <cuda_bf16.h>
#include <math.h>
#include <stdint.h>

#define BATCH 8
#define SEQ   2048
#define DIM   512
#define MTOT  (BATCH*SEQ)        // 16384

// ===========================================================================
// Scratch memory (single __device__ array; no allocation anywhere)
// ===========================================================================
#define SZ_X ((size_t)MTOT * DIM)                     // 8,388,608 elems
static const size_t O_XHI   = 0;                                // bf16 SZ_X
static const size_t O_XLO   = O_XHI   + SZ_X * 2;
static const size_t O_WHI   = O_XLO   + SZ_X * 2;               // bf16 3*DIM*DIM
static const size_t O_WLO   = O_WHI   + (size_t)3 * DIM * DIM * 2;
static const size_t O_QKVHI = O_WLO   + (size_t)3 * DIM * DIM * 2;  // bf16 3*SZ_X
static const size_t O_QKVLO = O_QKVHI + (size_t)3 * SZ_X * 2;
static const size_t O_VTHI  = O_QKVLO + (size_t)3 * SZ_X * 2;   // bf16 SZ_X (V^T)
static const size_t O_VTLO  = O_VTHI  + SZ_X * 2;
static const size_t O_S     = O_VTLO  + SZ_X * 2;               // fp32 B*S*S
static const size_t O_SHI   = O_S     + (size_t)BATCH * SEQ * SEQ * 4;
static const size_t O_SLO   = O_SHI   + (size_t)BATCH * SEQ * SEQ * 2;
static const size_t SCRATCH_TOTAL = O_SLO + (size_t)BATCH * SEQ * SEQ * 2;

__device__ __align__(1024) unsigned char g_scratch[SCRATCH_TOTAL];

// ===========================================================================
// PTX helpers (arch-agnostic: cp.async / ldmatrix / mma.sync only)
// ===========================================================================
__device__ __forceinline__ uint32_t smem_u32(const void* p) {
    uint32_t a;
    asm("{ .reg .u64 t; cvta.to.shared.u64 t, %1; cvt.u32.u64 %0, t; }"
        : "=r"(a) : "l"(p));
    return a;
}

#define SWZ128(x) ((x) ^ (((x) >> 3) & 0x70))

__device__ __forceinline__ void cp16(uint32_t dst, const void* src) {
    asm volatile("cp.async.cg.shared.global [%0], [%1], 16;\n"
                 :: "r"(dst), "l"(src));
}
__device__ __forceinline__ void cp_commit() {
    asm volatile("cp.async.commit_group;\n" ::: "memory");
}
template <int N> __device__ __forceinline__ void cp_wait() {
    asm volatile("cp.async.wait_group %0;\n" :: "n"(N) : "memory");
}

__device__ __forceinline__ void ldm_x4(uint32_t* r, uint32_t addr) {
    asm volatile("ldmatrix.sync.aligned.m8n8.x4.shared.b16 {%0,%1,%2,%3}, [%4];"
                 : "=r"(r[0]), "=r"(r[1]), "=r"(r[2]), "=r"(r[3]) : "r"(addr));
}

__device__ __forceinline__ void mma_bf16(float* c, const uint32_t* a,
                                         uint32_t b0, uint32_t b1) {
    asm volatile("mma.sync.aligned.m16n8k16.row.col.f32.bf16.bf16.f32 "
                 "{%0,%1,%2,%3}, {%4,%5,%6,%7}, {%8,%9}, {%0,%1,%2,%3};"
                 : "+f"(c[0]), "+f"(c[1]), "+f"(c[2]), "+f"(c[3])
                 : "r"(a[0]), "r"(a[1]), "r"(a[2]), "r"(a[3]), "r"(b0), "r"(b1));
}

// ===========================================================================
// HMMA GEMM:  C[M,N] = alpha * (Ahi@Bhi^T + Alo@Bhi^T + Ahi@Blo^T)   (bf16 NT)
// CTA tile 128(M) x 256(N), BK=64, 512 threads (16 warps, 32x64 warp tiles),
// double-buffered cp.async (2 x 96 KB stages).
// Epilogue: fp32*alpha if Chi==null, else bf16 hi/lo split.
// ===========================================================================
#define ST_BYTES 98304u          // Ah 16K | Al 16K | Bh 32K | Bl 32K
#define SMEM_GEMM (2 * 98304 + 1024)

__global__ __launch_bounds__(512, 1)
void hgemm3(const __nv_bfloat16* __restrict__ Ahi,
            const __nv_bfloat16* __restrict__ Alo,
            const __nv_bfloat16* __restrict__ Bhi,
            const __nv_bfloat16* __restrict__ Blo,
            float* __restrict__ C,
            __nv_bfloat16* __restrict__ Chi,
            __nv_bfloat16* __restrict__ Clo,
            int ldA, int ldB, int ldC, int kTiles,
            size_t sA, size_t sB, size_t sC, float alpha)
{
    extern __shared__ char smem_raw[];
    const uint32_t sbase = (smem_u32(smem_raw) + 1023u) & ~1023u;

    const int tid  = threadIdx.x;
    const int wid  = tid >> 5;
    const int lane = tid & 31;
    const int wm   = wid & 3;      // 4 M-warps -> 32 rows each
    const int wn   = wid >> 2;     // 4 N-warps -> 64 cols each

    const int row0 = blockIdx.y * 128;
    const int col0 = blockIdx.x * 256;

    Ahi += (size_t)blockIdx.z * sA;  Alo += (size_t)blockIdx.z * sA;
    Bhi += (size_t)blockIdx.z * sB;  Blo += (size_t)blockIdx.z * sB;

    float acc[2][8][4];
    #pragma unroll
    for (int mt = 0; mt < 2; mt++)
        #pragma unroll
        for (int j = 0; j < 8; j++)
            #pragma unroll
            for (int q = 0; q < 4; q++) acc[mt][j][q] = 0.f;

    // stage: [A_hi 16K][A_lo 16K][B_hi 32K][B_lo 32K]
    auto load_stage = [&](int t) {
        const int kk = t * 64;
        const uint32_t st = sbase + (uint32_t)(t & 1) * ST_BYTES;
        #pragma unroll
        for (int q = 0; q < 2; q++) {                 // A: 128 rows x 8 chunks
            int idx = tid + q * 512;
            int rr = idx >> 3, cc = idx & 7;
            uint32_t d = SWZ128((uint32_t)(rr * 128 + cc * 16));
            size_t oa = (size_t)(row0 + rr) * ldA + kk + cc * 8;
            cp16(st +          d, Ahi + oa);
            cp16(st + 16384u + d, Alo + oa);
        }
        #pragma unroll
        for (int q = 0; q < 4; q++) {                 // B: 256 rows x 8 chunks
            int idx = tid + q * 512;
            int rr = idx >> 3, cc = idx & 7;
            uint32_t d = SWZ128((uint32_t)(rr * 128 + cc * 16));
            size_t ob = (size_t)(col0 + rr) * ldB + kk + cc * 8;
            cp16(st + 32768u + d, Bhi + ob);
            cp16(st + 65536u + d, Blo + ob);
        }
        cp_commit();
    };

    load_stage(0);

    const uint32_t lrow = (uint32_t)(lane & 15);
    const uint32_t lcol = (uint32_t)((lane >> 4) * 16);

    for (int t = 0; t < kTiles; t++) {
        if (t + 1 < kTiles) {
            load_stage(t + 1);
            cp_wait<1>();
        } else {
            cp_wait<0>();
        }
        __syncthreads();

        const uint32_t st  = sbase + (uint32_t)(t & 1) * ST_BYTES;
        const uint32_t Ahs = st;
        const uint32_t Als = st + 16384u;
        const uint32_t Bhs = st + 32768u;
        const uint32_t Bls = st + 65536u;

        #pragma unroll
        for (int k16 = 0; k16 < 4; k16++) {
            const uint32_t koff = (uint32_t)(k16 * 32) + lcol;
            uint32_t ah[2][4], al[2][4];
            #pragma unroll
            for (int mt = 0; mt < 2; mt++) {
                uint32_t ro = SWZ128((uint32_t)((wm * 32 + mt * 16 + lrow) * 128) + koff);
                ldm_x4(ah[mt], Ahs + ro);
                ldm_x4(al[mt], Als + ro);
            }
            uint32_t bh[4][4], bl[4][4];
            #pragma unroll
            for (int ng = 0; ng < 4; ng++) {
                uint32_t ro = SWZ128((uint32_t)((wn * 64 + ng * 16 + lrow) * 128) + koff);
                ldm_x4(bh[ng], Bhs + ro);
                ldm_x4(bl[ng], Bls + ro);
            }
            #pragma unroll
            for (int mt = 0; mt < 2; mt++)
                #pragma unroll
                for (int j = 0; j < 8; j++) {
                    const int ng = j >> 1;
                    const int b0 = (j & 1) ? 1 : 0, b1 = (j & 1) ? 3 : 2;
                    mma_bf16(acc[mt][j], ah[mt], bh[ng][b0], bh[ng][b1]);
                    mma_bf16(acc[mt][j], al[mt], bh[ng][b0], bh[ng][b1]);
                    mma_bf16(acc[mt][j], ah[mt], bl[ng][b0], bl[ng][b1]);
                }
        }
        __syncthreads();
    }

    // Epilogue
    const int er = lane >> 2;
    const int ec = (lane & 3) * 2;
    if (Chi) {
        Chi += (size_t)blockIdx.z * sC;
        Clo += (size_t)blockIdx.z * sC;
        #pragma unroll
        for (int mt = 0; mt < 2; mt++) {
            const int rb = row0 + wm * 32 + mt * 16 + er;
            #pragma unroll
            for (int j = 0; j < 8; j++) {
                const int cb = col0 + wn * 64 + j * 8 + ec;
                #pragma unroll
                for (int h = 0; h < 2; h++) {
                    float vx = acc[mt][j][2 * h + 0];
                    float vy = acc[mt][j][2 * h + 1];
                    __nv_bfloat162 H, L;
                    H.x = __float2bfloat16(vx);
                    H.y = __float2bfloat16(vy);
                    L.x = __float2bfloat16(vx - __bfloat162float(H.x));
                    L.y = __float2bfloat16(vy - __bfloat162float(H.y));
                    const size_t o = (size_t)(rb + 8 * h) * ldC + cb;
                    *(__nv_bfloat162*)(Chi + o) = H;
                    *(__nv_bfloat162*)(Clo + o) = L;
                }
            }
        }
    } else {
        C += (size_t)blockIdx.z * sC;
        #pragma unroll
        for (int mt = 0; mt < 2; mt++) {
            const int rb = row0 + wm * 32 + mt * 16 + er;
            #pragma unroll
            for (int j = 0; j < 8; j++) {
                const int cb = col0 + wn * 64 + j * 8 + ec;
                float2 v0 = make_float2(alpha * acc[mt][j][0], alpha * acc[mt][j][1]);
                float2 v1 = make_float2(alpha * acc[mt][j][2], alpha * acc[mt][j][3]);
                *(float2*)(C + (size_t)rb * ldC + cb)       = v0;
                *(float2*)(C + (size_t)(rb + 8) * ldC + cb) = v1;
            }
        }
    }
}

// ===========================================================================
// fp32 -> (bf16 hi, bf16 lo) elementwise split, 4 elems/thread
// ===========================================================================
__global__ __launch_bounds__(256)
void split2(const float* __restrict__ src, __nv_bfloat16* __restrict__ hi,
            __nv_bfloat16* __restrict__ lo, size_t n4)
{
    size_t i = (size_t)blockIdx.x * 256 + threadIdx.x;
    if (i >= n4) return;
    float4 v = ((const float4*)src)[i];
    __nv_bfloat16 h0 = __float2bfloat16(v.x);
    __nv_bfloat16 h1 = __float2bfloat16(v.y);
    __nv_bfloat16 h2 = __float2bfloat16(v.z);
    __nv_bfloat16 h3 = __float2bfloat16(v.w);
    __nv_bfloat162 H0; H0.x = h0; H0.y = h1;
    __nv_bfloat162 H1; H1.x = h2; H1.y = h3;
    ((__nv_bfloat162*)hi)[2 * i + 0] = H0;
    ((__nv_bfloat162*)hi)[2 * i + 1] = H1;
    __nv_bfloat162 L0, L1;
    L0.x = __float2bfloat16(v.x - __bfloat162float(h0));
    L0.y = __float2bfloat16(v.y - __bfloat162float(h1));
    L1.x = __float2bfloat16(v.z - __bfloat162float(h2));
    L1.y = __float2bfloat16(v.w - __bfloat162float(h3));
    ((__nv_bfloat162*)lo)[2 * i + 0] = L0;
    ((__nv_bfloat162*)lo)[2 * i + 1] = L1;
}

// ===========================================================================
// bf16 [b,s,d] -> bf16 [b,d,s] transpose (64x64 tiles). grid.z = batch*2
// selects hi (z even) or lo (z odd) tensor pair.
// ===========================================================================
__global__ __launch_bounds__(256)
void transpose_bf16(const __nv_bfloat16* __restrict__ srcHi,
                    __nv_bfloat16* __restrict__ dstHi,
                    const __nv_bfloat16* __restrict__ srcLo,
                    __nv_bfloat16* __restrict__ dstLo)
{
    __shared__ __nv_bfloat16 t[64][65];
    const int z = blockIdx.z;
    const int b = z >> 1;
    const __nv_bfloat16* src = (z & 1) ? srcLo : srcHi;
    __nv_bfloat16*       dst = (z & 1) ? dstLo : dstHi;
    const int s0 = blockIdx.x * 64, d0 = blockIdx.y * 64;
    const int tid = threadIdx.x;
    src += (size_t)b * SEQ * DIM;
    dst += (size_t)b * DIM * SEQ;

    #pragma unroll
    for (int q = 0; q < 8; q++) {
        int i = tid + q * 256;
        int row = i >> 5, cp = i & 31;
        __nv_bfloat162 v = *(const __nv_bfloat162*)
            (src + (size_t)(s0 + row) * DIM + d0 + cp * 2);
        t[row][cp * 2 + 0] = v.x;
        t[row][cp * 2 + 1] = v.y;
    }
    __syncthreads();
    #pragma unroll
    for (int q = 0; q < 8; q++) {
        int i = tid + q * 256;
        int drow = i >> 5, sp = i & 31;
        __nv_bfloat162 o;
        o.x = t[sp * 2 + 0][drow];
        o.y = t[sp * 2 + 1][drow];
        *(__nv_bfloat162*)(dst + (size_t)(d0 + drow) * SEQ + s0 + sp * 2) = o;
    }
}

// ===========================================================================
// Row softmax (row held in registers) fused with bf16 hi/lo split output
// ===========================================================================
__global__ __launch_bounds__(256)
void softmax_split(const float* __restrict__ S, __nv_bfloat16* __restrict__ hi,
                   __nv_bfloat16* __restrict__ lo)
{
    __shared__ float red_m[8];
    __shared__ float red_s[8];
    const size_t base = (size_t)blockIdx.x * SEQ;
    const int tid  = threadIdx.x;
    const int wid  = tid >> 5;
    const int lane = tid & 31;

    const float4* row4 = (const float4*)(S + base);
    float4 v0 = row4[tid];
    float4 v1 = row4[tid + 256];

    float m = fmaxf(fmaxf(fmaxf(v0.x, v0.y), fmaxf(v0.z, v0.w)),
                    fmaxf(fmaxf(v1.x, v1.y), fmaxf(v1.z, v1.w)));
    #pragma unroll
    for (int o = 16; o > 0; o >>= 1) m = fmaxf(m, __shfl_xor_sync(~0u, m, o));
    if (lane == 0) red_m[wid] = m;
    __syncthreads();
    m = red_m[0];
    #pragma unroll
    for (int i = 1; i < 8; i++) m = fmaxf(m, red_m[i]);

    v0.x = __expf(v0.x - m); v0.y = __expf(v0.y - m);
    v0.z = __expf(v0.z - m); v0.w = __expf(v0.w - m);
    v1.x = __expf(v1.x - m); v1.y = __expf(v1.y - m);
    v1.z = __expf(v1.z - m); v1.w = __expf(v1.w - m);

    float s = v0.x + v0.y + v0.z + v0.w + v1.x + v1.y + v1.z + v1.w;
    #pragma unroll
    for (int o = 16; o > 0; o >>= 1) s += __shfl_xor_sync(~0u, s, o);
    if (lane == 0) red_s[wid] = s;
    __syncthreads();
    s = red_s[0];
    #pragma unroll
    for (int i = 1; i < 8; i++) s += red_s[i];
    const float inv = 1.f / s;

    auto emit = [&](float4 v, int c0) {
        float a0 = v.x * inv, a1 = v.y * inv, a2 = v.z * inv, a3 = v.w * inv;
        __nv_bfloat162 H0, H1, L0, L1;
        H0.x = __float2bfloat16(a0); H0.y = __float2bfloat16(a1);
        H1.x = __float2bfloat16(a2); H1.y = __float2bfloat16(a3);
        L0.x = __float2bfloat16(a0 - __bfloat162float(H0.x));
        L0.y = __float2bfloat16(a1 - __bfloat162float(H0.y));
        L1.x = __float2bfloat16(a2 - __bfloat162float(H1.x));
        L1.y = __float2bfloat16(a3 - __bfloat162float(H1.y));
        *(__nv_bfloat162*)(hi + base + c0)     = H0;
        *(__nv_bfloat162*)(hi + base + c0 + 2) = H1;
        *(__nv_bfloat162*)(lo + base + c0)     = L0;
        *(__nv_bfloat162*)(lo + base + c0 + 2) = L1;
    };
    emit(v0, tid * 4);
    emit(v1, (tid + 256) * 4);
}

// ===========================================================================
extern "C" void kernel_launch(void* const* d_in, const int* in_sizes, int n_in,
                              void* d_out, int out_size)
{
    const float* x  = (const float*)d_in[0];
    const float* Wq = (const float*)d_in[1];
    const float* Wk = (const float*)d_in[2];
    const float* Wv = (const float*)d_in[3];
    float* out = (float*)d_out;

    cudaFuncSetAttribute(hgemm3, cudaFuncAttributeMaxDynamicSharedMemorySize,
                         SMEM_GEMM);

    unsigned char* base;
    cudaGetSymbolAddress((void**)&base, g_scratch);

    __nv_bfloat16* xhi   = (__nv_bfloat16*)(base + O_XHI);
    __nv_bfloat16* xlo   = (__nv_bfloat16*)(base + O_XLO);
    __nv_bfloat16* whi   = (__nv_bfloat16*)(base + O_WHI);
    __nv_bfloat16* wlo   = (__nv_bfloat16*)(base + O_WLO);
    __nv_bfloat16* qkvhi = (__nv_bfloat16*)(base + O_QKVHI);
    __nv_bfloat16* qkvlo = (__nv_bfloat16*)(base + O_QKVLO);
    __nv_bfloat16* vthi  = (__nv_bfloat16*)(base + O_VTHI);
    __nv_bfloat16* vtlo  = (__nv_bfloat16*)(base + O_VTLO);
    float*         Sf    = (float*)(base + O_S);
    __nv_bfloat16* shi   = (__nv_bfloat16*)(base + O_SHI);
    __nv_bfloat16* slo   = (__nv_bfloat16*)(base + O_SLO);

    const float scale = 0.044194173824159216f;   // 1/sqrt(512)

    // 1. split x and the three weight matrices
    split2<<<(unsigned)(SZ_X / 4 / 256), 256>>>(x, xhi, xlo, SZ_X / 4);
    split2<<<DIM * DIM / 4 / 256, 256>>>(Wq, whi,                 wlo,                 DIM * DIM / 4);
    split2<<<DIM * DIM / 4 / 256, 256>>>(Wk, whi + DIM * DIM,     wlo + DIM * DIM,     DIM * DIM / 4);
    split2<<<DIM * DIM / 4 / 256, 256>>>(Wv, whi + 2 * DIM * DIM, wlo + 2 * DIM * DIM, DIM * DIM / 4);

    // 2. QKV projections, split bf16 epilogue (grid.z batches the 3 weights)
    {
        dim3 g(DIM / 256, MTOT / 128, 3);
        hgemm3<<<g, 512, SMEM_GEMM>>>(xhi, xlo, whi, wlo,
                                      nullptr, qkvhi, qkvlo,
                                      DIM, DIM, DIM, DIM / 64,
                                      0, (size_t)DIM * DIM, SZ_X, 1.0f);
    }

    // 3. transpose V (hi and lo) -> V^T
    {
        dim3 g(SEQ / 64, DIM / 64, BATCH * 2);
        transpose_bf16<<<g, 256>>>(qkvhi + 2 * SZ_X, vthi, qkvlo + 2 * SZ_X, vtlo);
    }

    // 4. scores = Q @ K^T * scale  (fp32 epilogue)
    {
        dim3 g(SEQ / 256, SEQ / 128, BATCH);
        hgemm3<<<g, 512, SMEM_GEMM>>>(qkvhi, qkvlo, qkvhi + SZ_X, qkvlo + SZ_X,
                                      Sf, nullptr, nullptr,
                                      DIM, DIM, SEQ, DIM / 64,
                                      (size_t)SEQ * DIM, (size_t)SEQ * DIM,
                                      (size_t)SEQ * SEQ, scale);
    }

    // 5. softmax + split
    softmax_split<<<BATCH * SEQ, 256>>>(Sf, shi, slo);

    // 6. out = attn @ V  (V pre-transposed -> NT form, fp32 epilogue)
    {
        dim3 g(DIM / 256, SEQ / 128, BATCH);
        hgemm3<<<g, 512, SMEM_GEMM>>>(shi, slo, vthi, vtlo,
                                      out, nullptr, nullptr,
                                      SEQ, SEQ, DIM, SEQ / 64,
                                      (size_t)SEQ * SEQ, (size_t)DIM * SEQ,
                                      (size_t)SEQ * DIM, 1.0f);
    }
}